// round 8
// baseline (speedup 1.0000x reference)
#include <cuda_runtime.h>
#include <stdint.h>

// Shapes (fixed by reference setup_inputs):
//   ids_uid   : [4096, 200] int32
//   ids_item  : [4096, 50]  int32
//   table_uid : [1000000, 64]  float32
//   table_item: [100000, 128] float32
//   out       : [4096, 192] float32 (cols 0..63 uid sum-pool, 64..191 item mean-pool)
// PADDING_IDX = 0; mean denom clipped to >= 1.

#define B        4096
#define L_UID    200
#define L_ITEM   50
#define D_UID    64
#define D_ITEM   128
#define D_OUT    192
#define UID_CHUNKS 4                       // 200 / 4 = 50 ids per chunk-warp (R3 shape)
#define IDS_PER_CHUNK (L_UID / UID_CHUNKS) // 50
#define GROUP_W  (UID_CHUNKS + 1)          // 5 warps per output row

// ---------------------------------------------------------------------------
// Kernel 1: zero the uid columns of out (uid part accumulated via atomics).
// ---------------------------------------------------------------------------
__global__ __launch_bounds__(256)
void zero_uid_kernel(float* __restrict__ out)
{
    const int t   = blockIdx.x * blockDim.x + threadIdx.x;  // 0..65535
    const int row = t >> 4;
    const int q   = t & 15;
    *reinterpret_cast<float4*>(out + (size_t)row * D_OUT + q * 4) =
        make_float4(0.f, 0.f, 0.f, 0.f);
}

// ---------------------------------------------------------------------------
// Kernel 2: balanced gather/pool (R3 grid shape) with register-staged ids.
// Each warp pre-loads its 50 ids into 2 lane registers (2 coalesced LDGs),
// then a fully-unrolled loop gets each id via __shfl_sync. All 50 gathers are
// mutually independent -> deep MLP, no per-iteration id-load dependency.
// ---------------------------------------------------------------------------
__global__ __launch_bounds__(256, 6)
void emb_pool_kernel(const int*   __restrict__ ids_uid,
                     const int*   __restrict__ ids_item,
                     const float* __restrict__ t_uid,
                     const float* __restrict__ t_item,
                     float*       __restrict__ out)
{
    const int gw   = (blockIdx.x * blockDim.x + threadIdx.x) >> 5;
    const int lane = threadIdx.x & 31;
    const int group = gw / GROUP_W;
    const int k     = gw - group * GROUP_W;
    if (group >= B) return;

    if (k < UID_CHUNKS) {
        // ----- uid partial: sum pool over 50 ids, lane owns 2 floats -----
        const int* __restrict__ ids =
            ids_uid + (size_t)group * L_UID + k * IDS_PER_CHUNK;

        // Stage 50 ids into lane registers: 2 coalesced LDGs.
        const int id_a = __ldg(ids + lane);                       // ids[0..31]
        const int ib   = 32 + lane;
        const int id_b = (ib < IDS_PER_CHUNK) ? __ldg(ids + ib) : 0;  // ids[32..49]

        const int col = lane * 2;
        float ax = 0.f, ay = 0.f;

        #pragma unroll
        for (int i = 0; i < IDS_PER_CHUNK; ++i) {
            const int id = __shfl_sync(0xffffffffu,
                                       (i < 32) ? id_a : id_b, i & 31);
            const float2 v = *reinterpret_cast<const float2*>(
                t_uid + (size_t)id * D_UID + col);
            const float m = (id != 0) ? 1.0f : 0.0f;
            ax = fmaf(m, v.x, ax);
            ay = fmaf(m, v.y, ay);
        }

        float* dst = out + (size_t)group * D_OUT + col;
        atomicAdd(dst,     ax);                                   // REDG.ADD.F32
        atomicAdd(dst + 1, ay);

    } else {
        // ----- item: mean pool over 50 ids, lane owns 4 floats -----
        const int* __restrict__ ids = ids_item + (size_t)group * L_ITEM;

        const int id_a = __ldg(ids + lane);                       // ids[0..31]
        const int ib   = 32 + lane;
        const int id_b = (ib < L_ITEM) ? __ldg(ids + ib) : 0;     // ids[32..49]

        const int col = lane * 4;
        float ax = 0.f, ay = 0.f, az = 0.f, aw = 0.f;
        int cnt = 0;

        #pragma unroll
        for (int i = 0; i < L_ITEM; ++i) {
            const int id = __shfl_sync(0xffffffffu,
                                       (i < 32) ? id_a : id_b, i & 31);
            const float4 v = *reinterpret_cast<const float4*>(
                t_item + (size_t)id * D_ITEM + col);              // LDG.128
            const float m = (id != 0) ? 1.0f : 0.0f;
            cnt += (id != 0);
            ax = fmaf(m, v.x, ax);
            ay = fmaf(m, v.y, ay);
            az = fmaf(m, v.z, az);
            aw = fmaf(m, v.w, aw);
        }

        const float inv = 1.0f / (float)max(cnt, 1);
        float4 r;
        r.x = ax * inv; r.y = ay * inv; r.z = az * inv; r.w = aw * inv;
        *reinterpret_cast<float4*>(out + (size_t)group * D_OUT + D_UID + col) = r;
    }
}

extern "C" void kernel_launch(void* const* d_in, const int* in_sizes, int n_in,
                              void* d_out, int out_size)
{
    (void)in_sizes; (void)n_in; (void)out_size;
    const int*   ids_uid  = (const int*)  d_in[0];
    const int*   ids_item = (const int*)  d_in[1];
    const float* t_uid    = (const float*)d_in[2];
    const float* t_item   = (const float*)d_in[3];
    float*       out      = (float*)d_out;

    // Zero uid region: 65536 threads.
    zero_uid_kernel<<<256, 256>>>(out);

    // Main: 4096 groups * 5 warps = 20480 warps -> 2560 blocks of 256 threads.
    const int warps_total = B * GROUP_W;
    const int blocks = (warps_total * 32) / 256;   // 2560
    emb_pool_kernel<<<blocks, 256>>>(ids_uid, ids_item, t_uid, t_item, out);
}

// round 10
// speedup vs baseline: 1.2731x; 1.2731x over previous
#include <cuda_runtime.h>
#include <stdint.h>

// Shapes (fixed by reference setup_inputs):
//   ids_uid   : [4096, 200] int32
//   ids_item  : [4096, 50]  int32
//   table_uid : [1000000, 64]  float32   (256 MB -> streamed, weak reuse)
//   table_item: [100000, 128] float32    (51 MB  -> fits L2, ~2x reuse)
//   out       : [4096, 192] float32 (cols 0..63 uid sum-pool, 64..191 item mean-pool)
// PADDING_IDX = 0; mean denom clipped to >= 1.

#define B        4096
#define L_UID    200
#define L_ITEM   50
#define D_UID    64
#define D_ITEM   128
#define D_OUT    192
#define UID_CHUNKS 4                       // 200 / 4 = 50 ids per chunk-warp (R3 shape)
#define IDS_PER_CHUNK (L_UID / UID_CHUNKS) // 50
#define GROUP_W  (UID_CHUNKS + 1)          // 5 warps per output row

// L2 eviction policies via createpolicy + cache_hint (valid for any ld width).
__device__ __forceinline__ uint64_t policy_evict_first()
{
    uint64_t pol;
    asm("createpolicy.fractional.L2::evict_first.b64 %0, 1.0;" : "=l"(pol));
    return pol;
}
__device__ __forceinline__ uint64_t policy_evict_last()
{
    uint64_t pol;
    asm("createpolicy.fractional.L2::evict_last.b64 %0, 1.0;" : "=l"(pol));
    return pol;
}

// uid table: streaming load, evict_first (don't thrash the item table).
__device__ __forceinline__ float2 ldg_f2_hint(const float* p, uint64_t pol)
{
    float2 v;
    asm volatile("ld.global.nc.L2::cache_hint.v2.f32 {%0,%1}, [%2], %3;"
                 : "=f"(v.x), "=f"(v.y) : "l"(p), "l"(pol));
    return v;
}

// item table: evict_last (keep the 51 MB hot table resident in 126 MB L2).
__device__ __forceinline__ float4 ldg_f4_hint(const float* p, uint64_t pol)
{
    float4 v;
    asm volatile("ld.global.nc.L2::cache_hint.v4.f32 {%0,%1,%2,%3}, [%4], %5;"
                 : "=f"(v.x), "=f"(v.y), "=f"(v.z), "=f"(v.w)
                 : "l"(p), "l"(pol));
    return v;
}

// ---------------------------------------------------------------------------
// Kernel 1: zero the uid columns of out (uid part accumulated via atomics).
// ---------------------------------------------------------------------------
__global__ __launch_bounds__(256)
void zero_uid_kernel(float* __restrict__ out)
{
    const int t   = blockIdx.x * blockDim.x + threadIdx.x;  // 0..65535
    const int row = t >> 4;
    const int q   = t & 15;
    *reinterpret_cast<float4*>(out + (size_t)row * D_OUT + q * 4) =
        make_float4(0.f, 0.f, 0.f, 0.f);
}

// ---------------------------------------------------------------------------
// Kernel 2: balanced gather/pool — exact R3 structure (proven 43.7us) with
// L2 eviction-priority hints on the two table-gather paths.
// 5 warps per output row: k=0..3 uid chunks (50 ids, partial sum, atomicAdd),
// k=4 item row (50 ids, mean, direct store).
// ---------------------------------------------------------------------------
__global__ __launch_bounds__(256, 6)
void emb_pool_kernel(const int*   __restrict__ ids_uid,
                     const int*   __restrict__ ids_item,
                     const float* __restrict__ t_uid,
                     const float* __restrict__ t_item,
                     float*       __restrict__ out)
{
    const int gw   = (blockIdx.x * blockDim.x + threadIdx.x) >> 5;
    const int lane = threadIdx.x & 31;
    const int group = gw / GROUP_W;
    const int k     = gw - group * GROUP_W;
    if (group >= B) return;

    if (k < UID_CHUNKS) {
        // ----- uid partial: sum pool over 50 ids, lane owns 2 floats -----
        const int* __restrict__ ids =
            ids_uid + (size_t)group * L_UID + k * IDS_PER_CHUNK;
        const int col = lane * 2;
        const uint64_t pol = policy_evict_first();

        float ax = 0.f, ay = 0.f;

        #pragma unroll 5
        for (int i = 0; i < IDS_PER_CHUNK; ++i) {
            const int id = __ldg(ids + i);                   // warp-broadcast
            const float2 v = ldg_f2_hint(t_uid + (size_t)id * D_UID + col, pol);
            const float m = (id != 0) ? 1.0f : 0.0f;
            ax = fmaf(m, v.x, ax);
            ay = fmaf(m, v.y, ay);
        }

        float* dst = out + (size_t)group * D_OUT + col;
        atomicAdd(dst,     ax);                              // REDG.ADD.F32
        atomicAdd(dst + 1, ay);

    } else {
        // ----- item: mean pool over 50 ids, lane owns 4 floats -----
        const int* __restrict__ ids = ids_item + (size_t)group * L_ITEM;
        const int col = lane * 4;
        const uint64_t pol = policy_evict_last();

        float ax = 0.f, ay = 0.f, az = 0.f, aw = 0.f;
        int cnt = 0;

        #pragma unroll 5
        for (int i = 0; i < L_ITEM; ++i) {
            const int id = __ldg(ids + i);
            const float4 v = ldg_f4_hint(t_item + (size_t)id * D_ITEM + col, pol);
            const float m = (id != 0) ? 1.0f : 0.0f;
            cnt += (id != 0);
            ax = fmaf(m, v.x, ax);
            ay = fmaf(m, v.y, ay);
            az = fmaf(m, v.z, az);
            aw = fmaf(m, v.w, aw);
        }

        const float inv = 1.0f / (float)max(cnt, 1);
        float4 r;
        r.x = ax * inv; r.y = ay * inv; r.z = az * inv; r.w = aw * inv;
        *reinterpret_cast<float4*>(out + (size_t)group * D_OUT + D_UID + col) = r;
    }
}

extern "C" void kernel_launch(void* const* d_in, const int* in_sizes, int n_in,
                              void* d_out, int out_size)
{
    (void)in_sizes; (void)n_in; (void)out_size;
    const int*   ids_uid  = (const int*)  d_in[0];
    const int*   ids_item = (const int*)  d_in[1];
    const float* t_uid    = (const float*)d_in[2];
    const float* t_item   = (const float*)d_in[3];
    float*       out      = (float*)d_out;

    // Zero uid region: 65536 threads.
    zero_uid_kernel<<<256, 256>>>(out);

    // Main: 4096 groups * 5 warps = 20480 warps -> 2560 blocks of 256 threads.
    const int warps_total = B * GROUP_W;
    const int blocks = (warps_total * 32) / 256;   // 2560
    emb_pool_kernel<<<blocks, 256>>>(ids_uid, ids_item, t_uid, t_item, out);
}